// round 7
// baseline (speedup 1.0000x reference)
#include <cuda_runtime.h>
#include <math.h>

#define NN 100000
#define EE 1600000
#define HH 128
#define GG 256
#define CC 5
#define FIN 4

// -------- scratch (static device globals; no allocation) --------
__device__ float g_h[(size_t)NN * HH];    // activations
__device__ float g_agg[(size_t)NN * HH];  // aggregation buffer
__device__ float g_aggx[(size_t)NN * FIN];

__device__ int   g_deg[NN];
__device__ float g_dinv[NN];
__device__ int   g_indeg[NN];
__device__ int   g_rowptr[NN];
__device__ int   g_fill[NN];
__device__ int   g_col[EE];
__device__ float g_coef[EE];

__device__ int   g_bsums[128];
__device__ int   g_boff[128];

__device__ float g_pool[GG * HH];
__device__ int   g_cnt[GG];

__device__ int   g_is64;   // 1 if index tensors are int64, 0 if int32

// index loader that works for both int32 and int64 harness layouts
__device__ __forceinline__ int load_idx(const void* p, size_t i) {
    if (g_is64) return (int)((const long long*)p)[i];
    return ((const int*)p)[i];
}

// -------- dtype detection --------
// If edge_index is int64, the high 32-bit word of every element is 0
// (values are in [0, 100000)). If int32, odd words are random node ids.
__global__ void k_detect(const int* __restrict__ ei32) {
    if (threadIdx.x == 0 && blockIdx.x == 0) {
        int orv = 0;
        for (int i = 0; i < 1024; i++) orv |= ei32[2 * i + 1];
        g_is64 = (orv == 0) ? 1 : 0;
    }
}

// -------- init --------
__global__ void k_init() {
    int i = blockIdx.x * blockDim.x + threadIdx.x;
    if (i < NN) { g_deg[i] = 1; g_fill[i] = 0; }   // deg=1 accounts for self-loop
    if (i < GG * HH) g_pool[i] = 0.f;
    if (i < GG) g_cnt[i] = 0;
}

// -------- degree count over dst --------
__global__ void k_count(const void* __restrict__ ei) {
    int e = blockIdx.x * blockDim.x + threadIdx.x;
    if (e >= EE) return;
    int d = load_idx(ei, (size_t)EE + e);
    atomicAdd(&g_deg[d], 1);
}

__global__ void k_dinv() {
    int i = blockIdx.x * blockDim.x + threadIdx.x;
    if (i >= NN) return;
    int dg = g_deg[i];
    g_dinv[i] = rsqrtf((float)dg);
    g_indeg[i] = dg - 1;
}

// -------- prefix scan of indeg -> rowptr (3 stages) --------
#define SCAN_B 1024
__global__ void k_scan1() {
    __shared__ int sh[SCAN_B];
    int i = blockIdx.x * SCAN_B + threadIdx.x;
    int v = (i < NN) ? g_indeg[i] : 0;
    sh[threadIdx.x] = v;
    __syncthreads();
    for (int off = 1; off < SCAN_B; off <<= 1) {
        int t = (threadIdx.x >= off) ? sh[threadIdx.x - off] : 0;
        __syncthreads();
        sh[threadIdx.x] += t;
        __syncthreads();
    }
    if (i < NN) g_rowptr[i] = sh[threadIdx.x] - v;  // exclusive
    if (threadIdx.x == SCAN_B - 1) g_bsums[blockIdx.x] = sh[threadIdx.x];
}

__global__ void k_scan2(int nb) {
    if (threadIdx.x == 0) {
        int run = 0;
        for (int b = 0; b < nb; b++) { int v = g_bsums[b]; g_boff[b] = run; run += v; }
    }
}

__global__ void k_scan3() {
    int i = blockIdx.x * SCAN_B + threadIdx.x;
    if (i < NN) g_rowptr[i] += g_boff[blockIdx.x];
}

// -------- scatter edges into CSR (by dst) --------
__global__ void k_scatter(const void* __restrict__ ei) {
    int e = blockIdx.x * blockDim.x + threadIdx.x;
    if (e >= EE) return;
    int s = load_idx(ei, (size_t)e);
    int d = load_idx(ei, (size_t)EE + e);
    int pos = g_rowptr[d] + atomicAdd(&g_fill[d], 1);
    g_col[pos] = s;
    g_coef[pos] = g_dinv[s] * g_dinv[d];
}

// -------- layer-1 aggregation on raw x [N,4] (thread per node) --------
__global__ void k_aggx(const float* __restrict__ x) {
    int i = blockIdx.x * blockDim.x + threadIdx.x;
    if (i >= NN) return;
    float di = g_dinv[i];
    float4 xa = ((const float4*)x)[i];
    float w = di * di;
    float4 acc;
    acc.x = xa.x * w; acc.y = xa.y * w; acc.z = xa.z * w; acc.w = xa.w * w;
    int s0 = g_rowptr[i], cnt = g_indeg[i];
    for (int e = 0; e < cnt; e++) {
        int s = g_col[s0 + e];
        float c = g_coef[s0 + e];
        float4 xs = ((const float4*)x)[s];
        acc.x += c * xs.x; acc.y += c * xs.y; acc.z += c * xs.z; acc.w += c * xs.w;
    }
    ((float4*)g_aggx)[i] = acc;
}

// -------- layer-1 dense: h = relu(aggx @ W1 + b1) --------
__global__ void k_dense1(const float* __restrict__ W1, const float* __restrict__ b1) {
    __shared__ float w[FIN * HH];
    __shared__ float bb[HH];
    int tid = threadIdx.x;  // 128
    for (int t = tid; t < FIN * HH; t += 128) w[t] = W1[t];
    bb[tid] = b1[tid];
    __syncthreads();
    int base = blockIdx.x * 8;
    for (int nn = 0; nn < 8; nn++) {
        int i = base + nn;
        if (i >= NN) break;
        float4 xa = ((const float4*)g_aggx)[i];
        float v = xa.x * w[tid] + xa.y * w[HH + tid] + xa.z * w[2 * HH + tid]
                + xa.w * w[3 * HH + tid] + bb[tid];
        g_h[(size_t)i * HH + tid] = fmaxf(v, 0.f);
    }
}

// -------- aggregation on H=128 activations (warp per node) --------
__global__ void k_aggh() {
    int gt = blockIdx.x * blockDim.x + threadIdx.x;
    int i = gt >> 5;
    int lane = gt & 31;
    if (i >= NN) return;
    float di = g_dinv[i];
    float w = di * di;
    const float4* hrow = (const float4*)(g_h + (size_t)i * HH);
    float4 v0 = hrow[lane];
    float4 acc;
    acc.x = v0.x * w; acc.y = v0.y * w; acc.z = v0.z * w; acc.w = v0.w * w;
    int s0 = g_rowptr[i], cnt = g_indeg[i];
    int e = 0;
    for (; e + 2 <= cnt; e += 2) {
        int sA = g_col[s0 + e];     float cA = g_coef[s0 + e];
        int sB = g_col[s0 + e + 1]; float cB = g_coef[s0 + e + 1];
        float4 vA = ((const float4*)(g_h + (size_t)sA * HH))[lane];
        float4 vB = ((const float4*)(g_h + (size_t)sB * HH))[lane];
        acc.x += cA * vA.x; acc.y += cA * vA.y; acc.z += cA * vA.z; acc.w += cA * vA.w;
        acc.x += cB * vB.x; acc.y += cB * vB.y; acc.z += cB * vB.z; acc.w += cB * vB.w;
    }
    for (; e < cnt; e++) {
        int s = g_col[s0 + e]; float c = g_coef[s0 + e];
        float4 v = ((const float4*)(g_h + (size_t)s * HH))[lane];
        acc.x += c * v.x; acc.y += c * v.y; acc.z += c * v.z; acc.w += c * v.w;
    }
    ((float4*)(g_agg + (size_t)i * HH))[lane] = acc;
}

// -------- GEMM: g_h = relu(g_agg[N,128] @ W[128,128] + b) --------
#define BM 32
#define KC 32
__global__ void k_gemm_relu(const float* __restrict__ W, const float* __restrict__ b) {
    __shared__ float As[KC][BM + 1];
    __shared__ float Bs[KC][HH];
    int tid = threadIdx.x;        // 256
    int tcol = tid & 31;          // col-group: cols 4*tcol..4*tcol+3
    int trow = tid >> 5;          // row-group: rows 4*trow..4*trow+3
    int rowbase = blockIdx.x * BM;
    float4 acc[4];
#pragma unroll
    for (int m = 0; m < 4; m++) { acc[m].x = acc[m].y = acc[m].z = acc[m].w = 0.f; }

    for (int k0 = 0; k0 < HH; k0 += KC) {
        for (int t = tid; t < BM * KC; t += 256) {
            int m = t / KC, k = t % KC;
            int r = rowbase + m;
            As[k][m] = (r < NN) ? g_agg[(size_t)r * HH + k0 + k] : 0.f;
        }
        for (int t = tid; t < KC * HH / 4; t += 256) {
            int k = t / (HH / 4), c4 = t % (HH / 4);
            ((float4*)Bs[k])[c4] = ((const float4*)(W + (size_t)(k0 + k) * HH))[c4];
        }
        __syncthreads();
#pragma unroll
        for (int k = 0; k < KC; k++) {
            float a0 = As[k][trow * 4 + 0];
            float a1 = As[k][trow * 4 + 1];
            float a2 = As[k][trow * 4 + 2];
            float a3 = As[k][trow * 4 + 3];
            float4 bv = ((float4*)Bs[k])[tcol];
            acc[0].x += a0 * bv.x; acc[0].y += a0 * bv.y; acc[0].z += a0 * bv.z; acc[0].w += a0 * bv.w;
            acc[1].x += a1 * bv.x; acc[1].y += a1 * bv.y; acc[1].z += a1 * bv.z; acc[1].w += a1 * bv.w;
            acc[2].x += a2 * bv.x; acc[2].y += a2 * bv.y; acc[2].z += a2 * bv.z; acc[2].w += a2 * bv.w;
            acc[3].x += a3 * bv.x; acc[3].y += a3 * bv.y; acc[3].z += a3 * bv.z; acc[3].w += a3 * bv.w;
        }
        __syncthreads();
    }
    float4 bb = ((const float4*)b)[tcol];
#pragma unroll
    for (int m = 0; m < 4; m++) {
        int r = rowbase + trow * 4 + m;
        if (r < NN) {
            float4 o;
            o.x = fmaxf(acc[m].x + bb.x, 0.f);
            o.y = fmaxf(acc[m].y + bb.y, 0.f);
            o.z = fmaxf(acc[m].z + bb.z, 0.f);
            o.w = fmaxf(acc[m].w + bb.w, 0.f);
            ((float4*)(g_h + (size_t)r * HH))[tcol] = o;
        }
    }
}

// -------- mean pool (warp per node, float atomics) --------
__global__ void k_pool(const void* __restrict__ batch) {
    int gt = blockIdx.x * blockDim.x + threadIdx.x;
    int i = gt >> 5;
    int lane = gt & 31;
    if (i >= NN) return;
    int g = load_idx(batch, (size_t)i);
    float4 v = ((const float4*)(g_h + (size_t)i * HH))[lane];
    float* base = g_pool + (size_t)g * HH + lane * 4;
    atomicAdd(base + 0, v.x);
    atomicAdd(base + 1, v.y);
    atomicAdd(base + 2, v.z);
    atomicAdd(base + 3, v.w);
    if (lane == 0) atomicAdd(&g_cnt[g], 1);
}

// -------- classifier + sigmoid --------
__global__ void k_classify(const float* __restrict__ Wl, const float* __restrict__ bl,
                           float* __restrict__ out) {
    int t = blockIdx.x * blockDim.x + threadIdx.x;
    if (t >= GG * CC) return;
    int g = t / CC, c = t % CC;
    float inv = 1.f / fmaxf((float)g_cnt[g], 1.f);
    float s = bl[c];
    const float* p = g_pool + (size_t)g * HH;
#pragma unroll 8
    for (int j = 0; j < HH; j++) s += p[j] * inv * Wl[j * CC + c];
    out[t] = 1.f / (1.f + expf(-s));
}

extern "C" void kernel_launch(void* const* d_in, const int* in_sizes, int n_in,
                              void* d_out, int out_size) {
    const float* x   = (const float*)d_in[0];
    const void*  ei  = d_in[1];
    const void*  bat = d_in[2];
    const float* W1 = (const float*)d_in[3];
    const float* b1 = (const float*)d_in[4];
    const float* W2 = (const float*)d_in[5];
    const float* b2 = (const float*)d_in[6];
    const float* W3 = (const float*)d_in[7];
    const float* b3 = (const float*)d_in[8];
    const float* W4 = (const float*)d_in[9];
    const float* b4 = (const float*)d_in[10];
    const float* Wl = (const float*)d_in[11];
    const float* bl = (const float*)d_in[12];
    float* out = (float*)d_out;

    const int nb_scan = (NN + SCAN_B - 1) / SCAN_B;   // 98

    k_detect<<<1, 32>>>((const int*)ei);
    k_init<<<(NN + 255) / 256, 256>>>();
    k_count<<<(EE + 255) / 256, 256>>>(ei);
    k_dinv<<<(NN + 255) / 256, 256>>>();
    k_scan1<<<nb_scan, SCAN_B>>>();
    k_scan2<<<1, 32>>>(nb_scan);
    k_scan3<<<nb_scan, SCAN_B>>>();
    k_scatter<<<(EE + 255) / 256, 256>>>(ei);

    // layer 1: aggregate raw x, then dense
    k_aggx<<<(NN + 255) / 256, 256>>>(x);
    k_dense1<<<(NN + 7) / 8, 128>>>(W1, b1);

    // layers 2-4: aggregate(g_h) -> gemm+bias+relu -> g_h
    const float* Ws[3] = {W2, W3, W4};
    const float* bs[3] = {b2, b3, b4};
    for (int l = 0; l < 3; l++) {
        k_aggh<<<(NN * 32 + 255) / 256, 256>>>();
        k_gemm_relu<<<(NN + BM - 1) / BM, 256>>>(Ws[l], bs[l]);
    }

    k_pool<<<(NN * 32 + 255) / 256, 256>>>(bat);
    k_classify<<<(GG * CC + 255) / 256, 256>>>(Wl, bl, out);
}

// round 8
// speedup vs baseline: 1.2049x; 1.2049x over previous
#include <cuda_runtime.h>
#include <math.h>

#define NN 100000
#define EE 1600000
#define HH 128
#define GG 256
#define CC 5
#define FIN 4

// f32x2 packed math (Blackwell): ptxas never auto-fuses these
#define FMA_F32X2(d, a, b, c) \
    asm("fma.rn.f32x2 %0, %1, %2, %3;" : "=l"(d) : "l"(a), "l"(b), "l"(c))
#define DUP_F32X2(out, v) \
    asm("mov.b64 %0, {%1, %1};" : "=l"(out) : "f"(v))
#define UNPACK_F32X2(lo, hi, in) \
    asm("mov.b64 {%0, %1}, %2;" : "=f"(lo), "=f"(hi) : "l"(in))

// -------- scratch (static device globals; no allocation) --------
__device__ float g_h[(size_t)NN * HH];    // activations
__device__ float g_agg[(size_t)NN * HH];  // aggregation buffer
__device__ float g_aggx[(size_t)NN * FIN];

__device__ int   g_deg[NN];
__device__ float g_dinv[NN];
__device__ int   g_indeg[NN];
__device__ int   g_rowptr[NN];
__device__ int   g_fill[NN];
__device__ int   g_col[EE];
__device__ float g_coef[EE];

__device__ int   g_bsums[128];
__device__ int   g_boff[128];

__device__ float g_pool[GG * HH];
__device__ int   g_cnt[GG];

__device__ int   g_is64;   // 1 if index tensors are int64, 0 if int32

__device__ __forceinline__ int load_idx(const void* p, size_t i) {
    if (g_is64) return (int)((const long long*)p)[i];
    return ((const int*)p)[i];
}

// -------- dtype detection --------
__global__ void k_detect(const int* __restrict__ ei32) {
    if (threadIdx.x == 0 && blockIdx.x == 0) {
        int orv = 0;
        for (int i = 0; i < 1024; i++) orv |= ei32[2 * i + 1];
        g_is64 = (orv == 0) ? 1 : 0;
    }
}

// -------- init --------
__global__ void k_init() {
    int i = blockIdx.x * blockDim.x + threadIdx.x;
    if (i < NN) { g_deg[i] = 1; g_fill[i] = 0; }
    if (i < GG * HH) g_pool[i] = 0.f;
    if (i < GG) g_cnt[i] = 0;
}

// -------- degree count over dst --------
__global__ void k_count(const void* __restrict__ ei) {
    int e = blockIdx.x * blockDim.x + threadIdx.x;
    if (e >= EE) return;
    int d = load_idx(ei, (size_t)EE + e);
    atomicAdd(&g_deg[d], 1);
}

__global__ void k_dinv() {
    int i = blockIdx.x * blockDim.x + threadIdx.x;
    if (i >= NN) return;
    int dg = g_deg[i];
    g_dinv[i] = rsqrtf((float)dg);
    g_indeg[i] = dg - 1;
}

// -------- prefix scan of indeg -> rowptr --------
#define SCAN_B 1024
__global__ void k_scan1() {
    __shared__ int sh[SCAN_B];
    int i = blockIdx.x * SCAN_B + threadIdx.x;
    int v = (i < NN) ? g_indeg[i] : 0;
    sh[threadIdx.x] = v;
    __syncthreads();
    for (int off = 1; off < SCAN_B; off <<= 1) {
        int t = (threadIdx.x >= off) ? sh[threadIdx.x - off] : 0;
        __syncthreads();
        sh[threadIdx.x] += t;
        __syncthreads();
    }
    if (i < NN) g_rowptr[i] = sh[threadIdx.x] - v;  // exclusive
    if (threadIdx.x == SCAN_B - 1) g_bsums[blockIdx.x] = sh[threadIdx.x];
}

__global__ void k_scan2(int nb) {
    if (threadIdx.x == 0) {
        int run = 0;
        for (int b = 0; b < nb; b++) { int v = g_bsums[b]; g_boff[b] = run; run += v; }
    }
}

__global__ void k_scan3() {
    int i = blockIdx.x * SCAN_B + threadIdx.x;
    if (i < NN) g_rowptr[i] += g_boff[blockIdx.x];
}

// -------- scatter edges into CSR (by dst) --------
__global__ void k_scatter(const void* __restrict__ ei) {
    int e = blockIdx.x * blockDim.x + threadIdx.x;
    if (e >= EE) return;
    int s = load_idx(ei, (size_t)e);
    int d = load_idx(ei, (size_t)EE + e);
    int pos = g_rowptr[d] + atomicAdd(&g_fill[d], 1);
    g_col[pos] = s;
    g_coef[pos] = g_dinv[s] * g_dinv[d];
}

// -------- layer-1 aggregation on raw x [N,4] --------
__global__ void k_aggx(const float* __restrict__ x) {
    int i = blockIdx.x * blockDim.x + threadIdx.x;
    if (i >= NN) return;
    float di = g_dinv[i];
    float4 xa = ((const float4*)x)[i];
    float w = di * di;
    float4 acc;
    acc.x = xa.x * w; acc.y = xa.y * w; acc.z = xa.z * w; acc.w = xa.w * w;
    int s0 = g_rowptr[i], cnt = g_indeg[i];
    for (int e = 0; e < cnt; e++) {
        int s = g_col[s0 + e];
        float c = g_coef[s0 + e];
        float4 xs = ((const float4*)x)[s];
        acc.x += c * xs.x; acc.y += c * xs.y; acc.z += c * xs.z; acc.w += c * xs.w;
    }
    ((float4*)g_aggx)[i] = acc;
}

// -------- layer-1 dense: h = relu(aggx @ W1 + b1) --------
__global__ void k_dense1(const float* __restrict__ W1, const float* __restrict__ b1) {
    __shared__ float w[FIN * HH];
    __shared__ float bb[HH];
    int tid = threadIdx.x;  // 128
    for (int t = tid; t < FIN * HH; t += 128) w[t] = W1[t];
    bb[tid] = b1[tid];
    __syncthreads();
    int base = blockIdx.x * 8;
    for (int nn = 0; nn < 8; nn++) {
        int i = base + nn;
        if (i >= NN) break;
        float4 xa = ((const float4*)g_aggx)[i];
        float v = xa.x * w[tid] + xa.y * w[HH + tid] + xa.z * w[2 * HH + tid]
                + xa.w * w[3 * HH + tid] + bb[tid];
        g_h[(size_t)i * HH + tid] = fmaxf(v, 0.f);
    }
}

// -------- aggregation on H=128 activations (warp per node, 4-wide MLP) --------
__global__ void k_aggh() {
    int gt = blockIdx.x * blockDim.x + threadIdx.x;
    int i = gt >> 5;
    int lane = gt & 31;
    if (i >= NN) return;
    float di = g_dinv[i];
    float w = di * di;
    float4 v0 = ((const float4*)(g_h + (size_t)i * HH))[lane];
    float4 acc;
    acc.x = v0.x * w; acc.y = v0.y * w; acc.z = v0.z * w; acc.w = v0.w * w;
    int s0 = g_rowptr[i], cnt = g_indeg[i];
    int e = 0;
    for (; e + 4 <= cnt; e += 4) {
        int sA = g_col[s0 + e];     float cA = g_coef[s0 + e];
        int sB = g_col[s0 + e + 1]; float cB = g_coef[s0 + e + 1];
        int sC = g_col[s0 + e + 2]; float cC = g_coef[s0 + e + 2];
        int sD = g_col[s0 + e + 3]; float cD = g_coef[s0 + e + 3];
        float4 vA = ((const float4*)(g_h + (size_t)sA * HH))[lane];
        float4 vB = ((const float4*)(g_h + (size_t)sB * HH))[lane];
        float4 vC = ((const float4*)(g_h + (size_t)sC * HH))[lane];
        float4 vD = ((const float4*)(g_h + (size_t)sD * HH))[lane];
        acc.x += cA * vA.x; acc.y += cA * vA.y; acc.z += cA * vA.z; acc.w += cA * vA.w;
        acc.x += cB * vB.x; acc.y += cB * vB.y; acc.z += cB * vB.z; acc.w += cB * vB.w;
        acc.x += cC * vC.x; acc.y += cC * vC.y; acc.z += cC * vC.z; acc.w += cC * vC.w;
        acc.x += cD * vD.x; acc.y += cD * vD.y; acc.z += cD * vD.z; acc.w += cD * vD.w;
    }
    for (; e < cnt; e++) {
        int s = g_col[s0 + e]; float c = g_coef[s0 + e];
        float4 v = ((const float4*)(g_h + (size_t)s * HH))[lane];
        acc.x += c * v.x; acc.y += c * v.y; acc.z += c * v.z; acc.w += c * v.w;
    }
    ((float4*)(g_agg + (size_t)i * HH))[lane] = acc;
}

// -------- GEMM: g_h = relu(g_agg[N,128] @ W[128,128] + b), f32x2 packed --------
#define BM 64
#define KC 32
#define AS_STRIDE (BM + 4)   // 68 floats = 272B, keeps 16B alignment of row starts
__global__ void k_gemm_relu(const float* __restrict__ W, const float* __restrict__ b) {
    __shared__ float As[KC][AS_STRIDE];   // As[k][m]
    __shared__ float Bs[KC][HH];
    int tid = threadIdx.x;        // 256
    int tcol = tid & 31;          // cols 4*tcol .. 4*tcol+3
    int trow = tid >> 5;          // rows 8*trow .. 8*trow+7
    int rowbase = blockIdx.x * BM;

    // acc[j][c]: f32x2 over rows (8*trow+2j, 8*trow+2j+1), col 4*tcol+c
    unsigned long long acc[4][4];
#pragma unroll
    for (int j = 0; j < 4; j++)
#pragma unroll
        for (int c = 0; c < 4; c++) acc[j][c] = 0ull;

    for (int k0 = 0; k0 < HH; k0 += KC) {
        // A chunk: 64 rows x 32 k, float4 global loads (coalesced), transposed into As[k][m]
#pragma unroll
        for (int it = 0; it < 2; it++) {
            int idx4 = tid + it * 256;           // [0,512)
            int m = idx4 >> 3, kq = idx4 & 7;
            int r = rowbase + m;
            float4 v = (r < NN) ? ((const float4*)(g_agg + (size_t)r * HH + k0))[kq]
                                : make_float4(0.f, 0.f, 0.f, 0.f);
            As[kq * 4 + 0][m] = v.x;
            As[kq * 4 + 1][m] = v.y;
            As[kq * 4 + 2][m] = v.z;
            As[kq * 4 + 3][m] = v.w;
        }
        // B chunk: 32 x 128 as float4 (coalesced)
#pragma unroll
        for (int it = 0; it < 4; it++) {
            int idx4 = tid + it * 256;           // [0,1024)
            int k = idx4 >> 5, c4 = idx4 & 31;
            ((float4*)Bs[k])[c4] = ((const float4*)(W + (size_t)(k0 + k) * HH))[c4];
        }
        __syncthreads();
#pragma unroll
        for (int k = 0; k < KC; k++) {
            // A row-pairs load directly as 64-bit packed (broadcast across warp)
            const unsigned long long* ap =
                (const unsigned long long*)&As[k][trow * 8];
            unsigned long long a0 = ap[0], a1 = ap[1], a2 = ap[2], a3 = ap[3];
            float4 bv = ((float4*)Bs[k])[tcol];
            unsigned long long b0, b1, b2, b3;
            DUP_F32X2(b0, bv.x); DUP_F32X2(b1, bv.y);
            DUP_F32X2(b2, bv.z); DUP_F32X2(b3, bv.w);
            FMA_F32X2(acc[0][0], a0, b0, acc[0][0]);
            FMA_F32X2(acc[0][1], a0, b1, acc[0][1]);
            FMA_F32X2(acc[0][2], a0, b2, acc[0][2]);
            FMA_F32X2(acc[0][3], a0, b3, acc[0][3]);
            FMA_F32X2(acc[1][0], a1, b0, acc[1][0]);
            FMA_F32X2(acc[1][1], a1, b1, acc[1][1]);
            FMA_F32X2(acc[1][2], a1, b2, acc[1][2]);
            FMA_F32X2(acc[1][3], a1, b3, acc[1][3]);
            FMA_F32X2(acc[2][0], a2, b0, acc[2][0]);
            FMA_F32X2(acc[2][1], a2, b1, acc[2][1]);
            FMA_F32X2(acc[2][2], a2, b2, acc[2][2]);
            FMA_F32X2(acc[2][3], a2, b3, acc[2][3]);
            FMA_F32X2(acc[3][0], a3, b0, acc[3][0]);
            FMA_F32X2(acc[3][1], a3, b1, acc[3][1]);
            FMA_F32X2(acc[3][2], a3, b2, acc[3][2]);
            FMA_F32X2(acc[3][3], a3, b3, acc[3][3]);
        }
        __syncthreads();
    }

    float4 bb = ((const float4*)b)[tcol];
#pragma unroll
    for (int j = 0; j < 4; j++) {
        float lo0, hi0, lo1, hi1, lo2, hi2, lo3, hi3;
        UNPACK_F32X2(lo0, hi0, acc[j][0]);
        UNPACK_F32X2(lo1, hi1, acc[j][1]);
        UNPACK_F32X2(lo2, hi2, acc[j][2]);
        UNPACK_F32X2(lo3, hi3, acc[j][3]);
        int r0 = rowbase + trow * 8 + 2 * j;
        if (r0 < NN) {
            float4 o;
            o.x = fmaxf(lo0 + bb.x, 0.f);
            o.y = fmaxf(lo1 + bb.y, 0.f);
            o.z = fmaxf(lo2 + bb.z, 0.f);
            o.w = fmaxf(lo3 + bb.w, 0.f);
            ((float4*)(g_h + (size_t)r0 * HH))[tcol] = o;
        }
        if (r0 + 1 < NN) {
            float4 o;
            o.x = fmaxf(hi0 + bb.x, 0.f);
            o.y = fmaxf(hi1 + bb.y, 0.f);
            o.z = fmaxf(hi2 + bb.z, 0.f);
            o.w = fmaxf(hi3 + bb.w, 0.f);
            ((float4*)(g_h + (size_t)(r0 + 1) * HH))[tcol] = o;
        }
    }
}

// -------- mean pool (warp per node, float atomics) --------
__global__ void k_pool(const void* __restrict__ batch) {
    int gt = blockIdx.x * blockDim.x + threadIdx.x;
    int i = gt >> 5;
    int lane = gt & 31;
    if (i >= NN) return;
    int g = load_idx(batch, (size_t)i);
    float4 v = ((const float4*)(g_h + (size_t)i * HH))[lane];
    float* base = g_pool + (size_t)g * HH + lane * 4;
    atomicAdd(base + 0, v.x);
    atomicAdd(base + 1, v.y);
    atomicAdd(base + 2, v.z);
    atomicAdd(base + 3, v.w);
    if (lane == 0) atomicAdd(&g_cnt[g], 1);
}

// -------- classifier + sigmoid --------
__global__ void k_classify(const float* __restrict__ Wl, const float* __restrict__ bl,
                           float* __restrict__ out) {
    int t = blockIdx.x * blockDim.x + threadIdx.x;
    if (t >= GG * CC) return;
    int g = t / CC, c = t % CC;
    float inv = 1.f / fmaxf((float)g_cnt[g], 1.f);
    float s = bl[c];
    const float* p = g_pool + (size_t)g * HH;
#pragma unroll 8
    for (int j = 0; j < HH; j++) s += p[j] * inv * Wl[j * CC + c];
    out[t] = 1.f / (1.f + expf(-s));
}

extern "C" void kernel_launch(void* const* d_in, const int* in_sizes, int n_in,
                              void* d_out, int out_size) {
    const float* x   = (const float*)d_in[0];
    const void*  ei  = d_in[1];
    const void*  bat = d_in[2];
    const float* W1 = (const float*)d_in[3];
    const float* b1 = (const float*)d_in[4];
    const float* W2 = (const float*)d_in[5];
    const float* b2 = (const float*)d_in[6];
    const float* W3 = (const float*)d_in[7];
    const float* b3 = (const float*)d_in[8];
    const float* W4 = (const float*)d_in[9];
    const float* b4 = (const float*)d_in[10];
    const float* Wl = (const float*)d_in[11];
    const float* bl = (const float*)d_in[12];
    float* out = (float*)d_out;

    const int nb_scan = (NN + SCAN_B - 1) / SCAN_B;   // 98

    k_detect<<<1, 32>>>((const int*)ei);
    k_init<<<(NN + 255) / 256, 256>>>();
    k_count<<<(EE + 255) / 256, 256>>>(ei);
    k_dinv<<<(NN + 255) / 256, 256>>>();
    k_scan1<<<nb_scan, SCAN_B>>>();
    k_scan2<<<1, 32>>>(nb_scan);
    k_scan3<<<nb_scan, SCAN_B>>>();
    k_scatter<<<(EE + 255) / 256, 256>>>(ei);

    k_aggx<<<(NN + 255) / 256, 256>>>(x);
    k_dense1<<<(NN + 7) / 8, 128>>>(W1, b1);

    const float* Ws[3] = {W2, W3, W4};
    const float* bs[3] = {b2, b3, b4};
    for (int l = 0; l < 3; l++) {
        k_aggh<<<(NN * 32 + 255) / 256, 256>>>();
        k_gemm_relu<<<(NN + BM - 1) / BM, 256>>>(Ws[l], bs[l]);
    }

    k_pool<<<(NN * 32 + 255) / 256, 256>>>(bat);
    k_classify<<<(GG * CC + 255) / 256, 256>>>(Wl, bl, out);
}

// round 9
// speedup vs baseline: 1.3123x; 1.0891x over previous
#include <cuda_runtime.h>
#include <cuda_fp16.h>
#include <math.h>

#define NN 100000
#define EE 1600000
#define HH 128
#define GG 256
#define CC 5
#define FIN 4

// f32x2 packed math (Blackwell): ptxas never auto-fuses these
#define FMA_F32X2(d, a, b, c) \
    asm("fma.rn.f32x2 %0, %1, %2, %3;" : "=l"(d) : "l"(a), "l"(b), "l"(c))
#define DUP_F32X2(out, v) \
    asm("mov.b64 %0, {%1, %1};" : "=l"(out) : "f"(v))
#define UNPACK_F32X2(lo, hi, in) \
    asm("mov.b64 {%0, %1}, %2;" : "=f"(lo), "=f"(hi) : "l"(in))

// -------- scratch (static device globals; no allocation) --------
__device__ float  g_h[(size_t)NN * HH];    // fp32 activations (pool reads this)
__device__ __half g_h16[(size_t)NN * HH];  // fp16 shadow for gathers
__device__ float  g_agg[(size_t)NN * HH];  // aggregation buffer
__device__ float  g_aggx[(size_t)NN * FIN];

__device__ int   g_deg[NN];
__device__ float g_dinv[NN];
__device__ int   g_indeg[NN];
__device__ int   g_rowptr[NN];
__device__ int   g_fill[NN];
__device__ int   g_col[EE];
__device__ float g_coef[EE];

__device__ int   g_bsums[128];
__device__ int   g_boff[128];

__device__ float g_pool[GG * HH];
__device__ int   g_cnt[GG];

__device__ int   g_is64;   // 1 if index tensors are int64, 0 if int32

__device__ __forceinline__ int load_idx(const void* p, size_t i) {
    if (g_is64) return (int)((const long long*)p)[i];
    return ((const int*)p)[i];
}

__device__ __forceinline__ float4 h4_to_f4(uint2 u) {
    __half2 h0 = *(__half2*)&u.x;
    __half2 h1 = *(__half2*)&u.y;
    float2 f0 = __half22float2(h0);
    float2 f1 = __half22float2(h1);
    return make_float4(f0.x, f0.y, f1.x, f1.y);
}

// -------- dtype detection (warp-parallel) --------
__global__ void k_detect(const int* __restrict__ ei32) {
    int lane = threadIdx.x;
    int orv = 0;
    for (int i = lane; i < 1024; i += 32) orv |= ei32[2 * i + 1];
#pragma unroll
    for (int off = 16; off; off >>= 1) orv |= __shfl_xor_sync(0xffffffffu, orv, off);
    if (lane == 0) g_is64 = (orv == 0) ? 1 : 0;
}

// -------- init --------
__global__ void k_init() {
    int i = blockIdx.x * blockDim.x + threadIdx.x;
    if (i < NN) { g_deg[i] = 1; g_fill[i] = 0; }
    if (i < GG * HH) g_pool[i] = 0.f;
    if (i < GG) g_cnt[i] = 0;
}

// -------- degree count over dst --------
__global__ void k_count(const void* __restrict__ ei) {
    int e = blockIdx.x * blockDim.x + threadIdx.x;
    if (e >= EE) return;
    int d = load_idx(ei, (size_t)EE + e);
    atomicAdd(&g_deg[d], 1);
}

__global__ void k_dinv() {
    int i = blockIdx.x * blockDim.x + threadIdx.x;
    if (i >= NN) return;
    int dg = g_deg[i];
    g_dinv[i] = rsqrtf((float)dg);
    g_indeg[i] = dg - 1;
}

// -------- prefix scan of indeg -> rowptr --------
#define SCAN_B 1024
__global__ void k_scan1() {
    __shared__ int sh[SCAN_B];
    int i = blockIdx.x * SCAN_B + threadIdx.x;
    int v = (i < NN) ? g_indeg[i] : 0;
    sh[threadIdx.x] = v;
    __syncthreads();
    for (int off = 1; off < SCAN_B; off <<= 1) {
        int t = (threadIdx.x >= off) ? sh[threadIdx.x - off] : 0;
        __syncthreads();
        sh[threadIdx.x] += t;
        __syncthreads();
    }
    if (i < NN) g_rowptr[i] = sh[threadIdx.x] - v;  // exclusive
    if (threadIdx.x == SCAN_B - 1) g_bsums[blockIdx.x] = sh[threadIdx.x];
}

__global__ void k_scan2(int nb) {
    if (threadIdx.x == 0) {
        int run = 0;
        for (int b = 0; b < nb; b++) { int v = g_bsums[b]; g_boff[b] = run; run += v; }
    }
}

__global__ void k_scan3() {
    int i = blockIdx.x * SCAN_B + threadIdx.x;
    if (i < NN) g_rowptr[i] += g_boff[blockIdx.x];
}

// -------- scatter edges into CSR (by dst) --------
__global__ void k_scatter(const void* __restrict__ ei) {
    int e = blockIdx.x * blockDim.x + threadIdx.x;
    if (e >= EE) return;
    int s = load_idx(ei, (size_t)e);
    int d = load_idx(ei, (size_t)EE + e);
    int pos = g_rowptr[d] + atomicAdd(&g_fill[d], 1);
    g_col[pos] = s;
    g_coef[pos] = g_dinv[s] * g_dinv[d];
}

// -------- layer-1 aggregation on raw x [N,4] --------
__global__ void k_aggx(const float* __restrict__ x) {
    int i = blockIdx.x * blockDim.x + threadIdx.x;
    if (i >= NN) return;
    float di = g_dinv[i];
    float4 xa = ((const float4*)x)[i];
    float w = di * di;
    float4 acc;
    acc.x = xa.x * w; acc.y = xa.y * w; acc.z = xa.z * w; acc.w = xa.w * w;
    int s0 = g_rowptr[i], cnt = g_indeg[i];
    for (int e = 0; e < cnt; e++) {
        int s = g_col[s0 + e];
        float c = g_coef[s0 + e];
        float4 xs = ((const float4*)x)[s];
        acc.x += c * xs.x; acc.y += c * xs.y; acc.z += c * xs.z; acc.w += c * xs.w;
    }
    ((float4*)g_aggx)[i] = acc;
}

// -------- layer-1 dense: h = relu(aggx @ W1 + b1), writes fp32 + fp16 --------
__global__ void k_dense1(const float* __restrict__ W1, const float* __restrict__ b1) {
    __shared__ float w[FIN * HH];
    __shared__ float bb[HH];
    int tid = threadIdx.x;  // 128
    for (int t = tid; t < FIN * HH; t += 128) w[t] = W1[t];
    bb[tid] = b1[tid];
    __syncthreads();
    int base = blockIdx.x * 8;
    for (int nn = 0; nn < 8; nn++) {
        int i = base + nn;
        if (i >= NN) break;
        float4 xa = ((const float4*)g_aggx)[i];
        float v = xa.x * w[tid] + xa.y * w[HH + tid] + xa.z * w[2 * HH + tid]
                + xa.w * w[3 * HH + tid] + bb[tid];
        v = fmaxf(v, 0.f);
        g_h[(size_t)i * HH + tid] = v;
        g_h16[(size_t)i * HH + tid] = __float2half_rn(v);
    }
}

// -------- aggregation on fp16 activations (warp per node, 4-wide MLP) --------
__global__ void k_aggh() {
    int gt = blockIdx.x * blockDim.x + threadIdx.x;
    int i = gt >> 5;
    int lane = gt & 31;
    if (i >= NN) return;
    float di = g_dinv[i];
    float w = di * di;
    uint2 u0 = ((const uint2*)(g_h16 + (size_t)i * HH))[lane];
    float4 v0 = h4_to_f4(u0);
    float4 acc;
    acc.x = v0.x * w; acc.y = v0.y * w; acc.z = v0.z * w; acc.w = v0.w * w;
    int s0 = g_rowptr[i], cnt = g_indeg[i];
    int e = 0;
    for (; e + 4 <= cnt; e += 4) {
        int sA = g_col[s0 + e];     float cA = g_coef[s0 + e];
        int sB = g_col[s0 + e + 1]; float cB = g_coef[s0 + e + 1];
        int sC = g_col[s0 + e + 2]; float cC = g_coef[s0 + e + 2];
        int sD = g_col[s0 + e + 3]; float cD = g_coef[s0 + e + 3];
        float4 vA = h4_to_f4(((const uint2*)(g_h16 + (size_t)sA * HH))[lane]);
        float4 vB = h4_to_f4(((const uint2*)(g_h16 + (size_t)sB * HH))[lane]);
        float4 vC = h4_to_f4(((const uint2*)(g_h16 + (size_t)sC * HH))[lane]);
        float4 vD = h4_to_f4(((const uint2*)(g_h16 + (size_t)sD * HH))[lane]);
        acc.x += cA * vA.x; acc.y += cA * vA.y; acc.z += cA * vA.z; acc.w += cA * vA.w;
        acc.x += cB * vB.x; acc.y += cB * vB.y; acc.z += cB * vB.z; acc.w += cB * vB.w;
        acc.x += cC * vC.x; acc.y += cC * vC.y; acc.z += cC * vC.z; acc.w += cC * vC.w;
        acc.x += cD * vD.x; acc.y += cD * vD.y; acc.z += cD * vD.z; acc.w += cD * vD.w;
    }
    for (; e < cnt; e++) {
        int s = g_col[s0 + e]; float c = g_coef[s0 + e];
        float4 v = h4_to_f4(((const uint2*)(g_h16 + (size_t)s * HH))[lane]);
        acc.x += c * v.x; acc.y += c * v.y; acc.z += c * v.z; acc.w += c * v.w;
    }
    ((float4*)(g_agg + (size_t)i * HH))[lane] = acc;
}

// -------- GEMM: h = relu(g_agg[N,128] @ W[128,128] + b), f32x2 packed --------
#define BM 64
#define KC 32
#define AS_STRIDE (BM + 4)
__global__ void k_gemm_relu(const float* __restrict__ W, const float* __restrict__ b) {
    __shared__ float As[KC][AS_STRIDE];   // As[k][m]
    __shared__ float Bs[KC][HH];
    int tid = threadIdx.x;        // 256
    int tcol = tid & 31;          // cols 4*tcol .. 4*tcol+3
    int trow = tid >> 5;          // rows 8*trow .. 8*trow+7
    int rowbase = blockIdx.x * BM;

    unsigned long long acc[4][4];
#pragma unroll
    for (int j = 0; j < 4; j++)
#pragma unroll
        for (int c = 0; c < 4; c++) acc[j][c] = 0ull;

    for (int k0 = 0; k0 < HH; k0 += KC) {
#pragma unroll
        for (int it = 0; it < 2; it++) {
            int idx4 = tid + it * 256;           // [0,512)
            int m = idx4 >> 3, kq = idx4 & 7;
            int r = rowbase + m;
            float4 v = (r < NN) ? ((const float4*)(g_agg + (size_t)r * HH + k0))[kq]
                                : make_float4(0.f, 0.f, 0.f, 0.f);
            As[kq * 4 + 0][m] = v.x;
            As[kq * 4 + 1][m] = v.y;
            As[kq * 4 + 2][m] = v.z;
            As[kq * 4 + 3][m] = v.w;
        }
#pragma unroll
        for (int it = 0; it < 4; it++) {
            int idx4 = tid + it * 256;           // [0,1024)
            int k = idx4 >> 5, c4 = idx4 & 31;
            ((float4*)Bs[k])[c4] = ((const float4*)(W + (size_t)(k0 + k) * HH))[c4];
        }
        __syncthreads();
#pragma unroll
        for (int k = 0; k < KC; k++) {
            const unsigned long long* ap =
                (const unsigned long long*)&As[k][trow * 8];
            unsigned long long a0 = ap[0], a1 = ap[1], a2 = ap[2], a3 = ap[3];
            float4 bv = ((float4*)Bs[k])[tcol];
            unsigned long long b0, b1, b2, b3;
            DUP_F32X2(b0, bv.x); DUP_F32X2(b1, bv.y);
            DUP_F32X2(b2, bv.z); DUP_F32X2(b3, bv.w);
            FMA_F32X2(acc[0][0], a0, b0, acc[0][0]);
            FMA_F32X2(acc[0][1], a0, b1, acc[0][1]);
            FMA_F32X2(acc[0][2], a0, b2, acc[0][2]);
            FMA_F32X2(acc[0][3], a0, b3, acc[0][3]);
            FMA_F32X2(acc[1][0], a1, b0, acc[1][0]);
            FMA_F32X2(acc[1][1], a1, b1, acc[1][1]);
            FMA_F32X2(acc[1][2], a1, b2, acc[1][2]);
            FMA_F32X2(acc[1][3], a1, b3, acc[1][3]);
            FMA_F32X2(acc[2][0], a2, b0, acc[2][0]);
            FMA_F32X2(acc[2][1], a2, b1, acc[2][1]);
            FMA_F32X2(acc[2][2], a2, b2, acc[2][2]);
            FMA_F32X2(acc[2][3], a2, b3, acc[2][3]);
            FMA_F32X2(acc[3][0], a3, b0, acc[3][0]);
            FMA_F32X2(acc[3][1], a3, b1, acc[3][1]);
            FMA_F32X2(acc[3][2], a3, b2, acc[3][2]);
            FMA_F32X2(acc[3][3], a3, b3, acc[3][3]);
        }
        __syncthreads();
    }

    float4 bb = ((const float4*)b)[tcol];
#pragma unroll
    for (int j = 0; j < 4; j++) {
        float lo0, hi0, lo1, hi1, lo2, hi2, lo3, hi3;
        UNPACK_F32X2(lo0, hi0, acc[j][0]);
        UNPACK_F32X2(lo1, hi1, acc[j][1]);
        UNPACK_F32X2(lo2, hi2, acc[j][2]);
        UNPACK_F32X2(lo3, hi3, acc[j][3]);
        int r0 = rowbase + trow * 8 + 2 * j;
        if (r0 < NN) {
            float4 o;
            o.x = fmaxf(lo0 + bb.x, 0.f);
            o.y = fmaxf(lo1 + bb.y, 0.f);
            o.z = fmaxf(lo2 + bb.z, 0.f);
            o.w = fmaxf(lo3 + bb.w, 0.f);
            ((float4*)(g_h + (size_t)r0 * HH))[tcol] = o;
            __half2 p0 = __floats2half2_rn(o.x, o.y);
            __half2 p1 = __floats2half2_rn(o.z, o.w);
            uint2 pk; pk.x = *(unsigned*)&p0; pk.y = *(unsigned*)&p1;
            ((uint2*)(g_h16 + (size_t)r0 * HH))[tcol] = pk;
        }
        if (r0 + 1 < NN) {
            float4 o;
            o.x = fmaxf(hi0 + bb.x, 0.f);
            o.y = fmaxf(hi1 + bb.y, 0.f);
            o.z = fmaxf(hi2 + bb.z, 0.f);
            o.w = fmaxf(hi3 + bb.w, 0.f);
            ((float4*)(g_h + (size_t)(r0 + 1) * HH))[tcol] = o;
            __half2 p0 = __floats2half2_rn(o.x, o.y);
            __half2 p1 = __floats2half2_rn(o.z, o.w);
            uint2 pk; pk.x = *(unsigned*)&p0; pk.y = *(unsigned*)&p1;
            ((uint2*)(g_h16 + (size_t)(r0 + 1) * HH))[tcol] = pk;
        }
    }
}

// -------- mean pool (warp per node, float atomics) --------
__global__ void k_pool(const void* __restrict__ batch) {
    int gt = blockIdx.x * blockDim.x + threadIdx.x;
    int i = gt >> 5;
    int lane = gt & 31;
    if (i >= NN) return;
    int g = load_idx(batch, (size_t)i);
    float4 v = ((const float4*)(g_h + (size_t)i * HH))[lane];
    float* base = g_pool + (size_t)g * HH + lane * 4;
    atomicAdd(base + 0, v.x);
    atomicAdd(base + 1, v.y);
    atomicAdd(base + 2, v.z);
    atomicAdd(base + 3, v.w);
    if (lane == 0) atomicAdd(&g_cnt[g], 1);
}

// -------- classifier + sigmoid --------
__global__ void k_classify(const float* __restrict__ Wl, const float* __restrict__ bl,
                           float* __restrict__ out) {
    int t = blockIdx.x * blockDim.x + threadIdx.x;
    if (t >= GG * CC) return;
    int g = t / CC, c = t % CC;
    float inv = 1.f / fmaxf((float)g_cnt[g], 1.f);
    float s = bl[c];
    const float* p = g_pool + (size_t)g * HH;
#pragma unroll 8
    for (int j = 0; j < HH; j++) s += p[j] * inv * Wl[j * CC + c];
    out[t] = 1.f / (1.f + expf(-s));
}

extern "C" void kernel_launch(void* const* d_in, const int* in_sizes, int n_in,
                              void* d_out, int out_size) {
    const float* x   = (const float*)d_in[0];
    const void*  ei  = d_in[1];
    const void*  bat = d_in[2];
    const float* W1 = (const float*)d_in[3];
    const float* b1 = (const float*)d_in[4];
    const float* W2 = (const float*)d_in[5];
    const float* b2 = (const float*)d_in[6];
    const float* W3 = (const float*)d_in[7];
    const float* b3 = (const float*)d_in[8];
    const float* W4 = (const float*)d_in[9];
    const float* b4 = (const float*)d_in[10];
    const float* Wl = (const float*)d_in[11];
    const float* bl = (const float*)d_in[12];
    float* out = (float*)d_out;

    const int nb_scan = (NN + SCAN_B - 1) / SCAN_B;   // 98

    k_detect<<<1, 32>>>((const int*)ei);
    k_init<<<(NN + 255) / 256, 256>>>();
    k_count<<<(EE + 255) / 256, 256>>>(ei);
    k_dinv<<<(NN + 255) / 256, 256>>>();
    k_scan1<<<nb_scan, SCAN_B>>>();
    k_scan2<<<1, 32>>>(nb_scan);
    k_scan3<<<nb_scan, SCAN_B>>>();
    k_scatter<<<(EE + 255) / 256, 256>>>(ei);

    k_aggx<<<(NN + 255) / 256, 256>>>(x);
    k_dense1<<<(NN + 7) / 8, 128>>>(W1, b1);

    const float* Ws[3] = {W2, W3, W4};
    const float* bs[3] = {b2, b3, b4};
    for (int l = 0; l < 3; l++) {
        k_aggh<<<(NN * 32 + 255) / 256, 256>>>();
        k_gemm_relu<<<(NN + BM - 1) / BM, 256>>>(Ws[l], bs[l]);
    }

    k_pool<<<(NN * 32 + 255) / 256, 256>>>(bat);
    k_classify<<<(GG * CC + 255) / 256, 256>>>(Wl, bl, out);
}